// round 10
// baseline (speedup 1.0000x reference)
#include <cuda_runtime.h>
#include <cstdint>
#include <math.h>

// ---------------- problem constants ----------------
#define Bsz 8192
#define Sdim 268
#define Hdim 1024
#define Rn 8
#define Adim 256
#define SPADK 320            // state/W0 logical K padded to mult of 64

// Quantization ranges (static, >=12-sigma headroom)
#define QMAX   32512.0f
#define R_W    0.16f
#define R_ST   8.0f
#define R_RELU 4.0f
#define R_TANH 1.0f
#define R_V2   4.0f

// ---------------- device scratch (allocation-free) ----------------
__device__ float  g_h[(size_t)Bsz * Hdim];
__device__ int8_t g_sp_hi[(size_t)Bsz * SPADK];
__device__ int8_t g_sp_x [(size_t)Bsz * SPADK * 2];
__device__ int8_t g_h_hi [(size_t)Bsz * Hdim];
__device__ int8_t g_h_x  [(size_t)Bsz * Hdim * 2];
__device__ int8_t g_u_hi [(size_t)Bsz * Hdim];
__device__ int8_t g_u_x  [(size_t)Bsz * Hdim * 2];
__device__ int8_t g_v2_hi[(size_t)Bsz * Adim];
__device__ int8_t g_v2_x [(size_t)Bsz * Adim * 2];
__device__ int8_t g_w0_hi[(size_t)Hdim * SPADK];
__device__ int8_t g_w0_x [(size_t)Hdim * SPADK * 2];
__device__ int8_t g_rw1_hi[(size_t)Rn * Hdim * Hdim];
__device__ int8_t g_rw1_x [(size_t)Rn * Hdim * Hdim * 2];
__device__ int8_t g_rw2_hi[(size_t)Rn * Hdim * Hdim];
__device__ int8_t g_rw2_x [(size_t)Rn * Hdim * Hdim * 2];
__device__ int8_t g_wf_hi[(size_t)Sdim * Hdim];
__device__ int8_t g_wf_x [(size_t)Sdim * Hdim * 2];
__device__ int8_t g_tain_hi[(size_t)Adim * Adim];
__device__ int8_t g_tain_x [(size_t)Adim * Adim * 2];
__device__ int8_t g_taout_hi[(size_t)Adim * Adim];
__device__ int8_t g_taout_x [(size_t)Adim * Adim * 2];

// ---------------- helpers ----------------
__device__ __forceinline__ uint32_t smem_u32(const void* p) {
    uint32_t a;
    asm("{ .reg .u64 t; cvta.to.shared.u64 t, %1; cvt.u32.u64 %0, t; }" : "=r"(a) : "l"(p));
    return a;
}
__device__ __forceinline__ void cp16(uint32_t dst, const void* src, uint32_t sz) {
    asm volatile("cp.async.cg.shared.global [%0], [%1], 16, %2;"
                 :: "r"(dst), "l"(src), "r"(sz) : "memory");
}
__device__ __forceinline__ void ldm4(uint32_t& r0, uint32_t& r1, uint32_t& r2, uint32_t& r3, uint32_t a) {
    asm volatile("ldmatrix.sync.aligned.m8n8.x4.shared.b16 {%0,%1,%2,%3}, [%4];"
                 : "=r"(r0), "=r"(r1), "=r"(r2), "=r"(r3) : "r"(a));
}
__device__ __forceinline__ void mma_s8(int* d, const uint32_t* a, const uint32_t* b) {
    asm volatile("mma.sync.aligned.m16n8k32.row.col.s32.s8.s8.s32 "
                 "{%0,%1,%2,%3}, {%4,%5,%6,%7}, {%8,%9}, {%0,%1,%2,%3};"
                 : "+r"(d[0]), "+r"(d[1]), "+r"(d[2]), "+r"(d[3])
                 : "r"(a[0]), "r"(a[1]), "r"(a[2]), "r"(a[3]), "r"(b[0]), "r"(b[1]));
}
// quantize x*invs to 16-bit fixed: q = hi*256 + lo, |hi|<=127, |lo|<=128
__device__ __forceinline__ void quant_split(float x, float invs, int8_t& hi, int8_t& lo) {
    int q = __float2int_rn(x * invs);
    q = max(-32512, min(32512, q));
    int h = (q + 128) >> 8;
    hi = (int8_t)h;
    lo = (int8_t)(q - (h << 8));
}

// ---------------- conversion: 16 logical k per thread ----------------
// hi buffer: K bytes/row. x buffer: 2K bytes/row, pairs:
//   aSide=1 -> [hi,lo]   aSide=0 -> [lo,hi]
__global__ void conv16(const float* __restrict__ src,
                       int8_t* __restrict__ dhi, int8_t* __restrict__ dx,
                       int rows, int src_ld, int src_cols, int Klog, int aSide, float invs)
{
    const int per = Klog >> 4;
    size_t n = (size_t)rows * per;
    size_t stride = (size_t)gridDim.x * blockDim.x;
    for (size_t i = (size_t)blockIdx.x * blockDim.x + threadIdx.x; i < n; i += stride) {
        int r = (int)(i / per);
        int k0 = (int)(i % per) * 16;
        const float* s = src + (size_t)r * src_ld + k0;
        int8_t oh[16], ox[32];
#pragma unroll
        for (int j = 0; j < 16; j++) {
            int k = k0 + j;
            float x = (k < src_cols) ? s[j] : 0.0f;
            int8_t hi, lo; quant_split(x, invs, hi, lo);
            oh[j] = hi;
            if (aSide) { ox[j*2] = hi; ox[j*2+1] = lo; }
            else       { ox[j*2] = lo; ox[j*2+1] = hi; }
        }
        *(int4*)(dhi + (size_t)r * Klog + k0) = *(const int4*)oh;
        int4* d = (int4*)(dx + ((size_t)r * Klog + k0) * 2);
        d[0] = ((const int4*)ox)[0]; d[1] = ((const int4*)ox)[1];
    }
}

// ---------------- s8 two-stream MMA GEMM ----------------
// C(MxN) = A(MxK)*B(NxK)^T with 16-bit fixed-point split:
//   acc_hh = A_hi . B_hi        (K bytes)
//   acc_x  = A_x . B_x          (2K bytes, [hi,lo].[lo,hi] = cross terms)
//   v = acc_hh*s_hh + acc_x*s_x + bias
// CTA 128x128, chunk = 64 logical k, 2-stage cp.async, 8 warps of 32x64.
#define RBH 80
#define RBX 144
#define OFF_BHI (128 * RBH)              // 10240
#define OFF_AX  (2 * 128 * RBH)          // 20480
#define OFF_BX  (OFF_AX + 128 * RBX)     // 38912
#define STAGEB  (OFF_BX + 128 * RBX)     // 57344
#define SMEM_DYN (2 * STAGEB)            // 114688

__global__ __launch_bounds__(256)
void s8_gemm(const int8_t* __restrict__ Ahi, const int8_t* __restrict__ Ax, int ldk,
             const int8_t* __restrict__ Bhi, const int8_t* __restrict__ Bx, int ldkb,
             int N, int Klog,
             float s_hh, float s_x,
             const float* __restrict__ bias,
             const float* __restrict__ aux, int aux_ld,
             float* __restrict__ Cf, int ldc,
             int8_t* __restrict__ Ohi, int8_t* __restrict__ Ox, int ldo, float oinv,
             int mode,
             const float* __restrict__ W0f32, const float* __restrict__ tptr)
{
    extern __shared__ char smem[];
    const uint32_t sbase = smem_u32(smem);
    const int tid = threadIdx.x;
    const int lane = tid & 31, wid = tid >> 5;
    const int bm = blockIdx.y * 128;
    const int bn = blockIdx.x * 128;
    const int warp_m = (wid & 3) * 32;
    const int warp_n = (wid >> 2) * 64;

    // ldmatrix per-lane offsets: hi tiles (80B rows) and x tiles (144B rows)
    uint32_t ah_off[2], bh_off[4], ax_off[2], bx_off[4];
#pragma unroll
    for (int t = 0; t < 2; t++) {
        int row = warp_m + t * 16 + (lane & 15);
        ah_off[t] = (uint32_t)row * RBH + (uint32_t)(lane >> 4) * 16;
        ax_off[t] = (uint32_t)row * RBX + (uint32_t)(lane >> 4) * 16;
    }
#pragma unroll
    for (int p = 0; p < 4; p++) {
        int row = warp_n + p * 16 + ((lane >> 4) << 3) + (lane & 7);
        uint32_t ch = (uint32_t)((lane >> 3) & 1) * 16;
        bh_off[p] = (uint32_t)row * RBH + ch;
        bx_off[p] = (uint32_t)row * RBX + ch;
    }

    int acc_hh[2][8][4], acc_x[2][8][4];
#pragma unroll
    for (int t = 0; t < 2; t++)
#pragma unroll
        for (int j = 0; j < 8; j++)
#pragma unroll
            for (int e = 0; e < 4; e++) { acc_hh[t][j][e] = 0; acc_x[t][j][e] = 0; }

    const int nch = Klog / 64;

#define ISSUE_LOADS(cc) do {                                                          \
        const int kh0 = (cc) * 64;                                                    \
        const uint32_t stg = sbase + ((cc) & 1) * STAGEB;                             \
        _Pragma("unroll")                                                             \
        for (int j = 0; j < 2; j++) {  /* A_hi: 128x64B */                            \
            int vid = tid + j * 256; int row = vid >> 2, kv = vid & 3;                \
            uint32_t d = stg + (uint32_t)row * RBH + (uint32_t)kv * 16;               \
            cp16(d, Ahi + (size_t)(bm + row) * ldk + kh0 + kv * 16, 16);              \
        }                                                                             \
        _Pragma("unroll")                                                             \
        for (int j = 0; j < 2; j++) {  /* B_hi */                                     \
            int vid = tid + j * 256; int row = vid >> 2, kv = vid & 3;                \
            int n0 = bn + row; int nc = n0 < N ? n0 : (N - 1);                        \
            uint32_t d = stg + OFF_BHI + (uint32_t)row * RBH + (uint32_t)kv * 16;     \
            cp16(d, Bhi + (size_t)nc * ldkb + kh0 + kv * 16, n0 < N ? 16u : 0u);      \
        }                                                                             \
        _Pragma("unroll")                                                             \
        for (int j = 0; j < 4; j++) {  /* A_x: 128x128B */                            \
            int vid = tid + j * 256; int row = vid >> 3, kv = vid & 7;                \
            uint32_t d = stg + OFF_AX + (uint32_t)row * RBX + (uint32_t)kv * 16;      \
            cp16(d, Ax + (size_t)(bm + row) * 2 * ldk + 2 * kh0 + kv * 16, 16);       \
        }                                                                             \
        _Pragma("unroll")                                                             \
        for (int j = 0; j < 4; j++) {  /* B_x */                                      \
            int vid = tid + j * 256; int row = vid >> 3, kv = vid & 7;                \
            int n0 = bn + row; int nc = n0 < N ? n0 : (N - 1);                        \
            uint32_t d = stg + OFF_BX + (uint32_t)row * RBX + (uint32_t)kv * 16;      \
            cp16(d, Bx + (size_t)nc * 2 * ldkb + 2 * kh0 + kv * 16, n0 < N ? 16u : 0u); \
        }                                                                             \
        asm volatile("cp.async.commit_group;" ::: "memory");                          \
    } while (0)

    ISSUE_LOADS(0);

    for (int c = 0; c < nch; c++) {
        if (c + 1 < nch) {
            ISSUE_LOADS(c + 1);
            asm volatile("cp.async.wait_group 1;" ::: "memory");
        } else {
            asm volatile("cp.async.wait_group 0;" ::: "memory");
        }
        __syncthreads();

        const uint32_t stg = sbase + (c & 1) * STAGEB;
        // hi . hi  (64 bytes of k -> 2 mma-k steps)
#pragma unroll
        for (int ks = 0; ks < 2; ks++) {
            uint32_t a[2][4];
            ldm4(a[0][0], a[0][1], a[0][2], a[0][3], stg + ah_off[0] + ks * 32);
            ldm4(a[1][0], a[1][1], a[1][2], a[1][3], stg + ah_off[1] + ks * 32);
            uint32_t bb[4][4];
#pragma unroll
            for (int p = 0; p < 4; p++)
                ldm4(bb[p][0], bb[p][1], bb[p][2], bb[p][3], stg + OFF_BHI + bh_off[p] + ks * 32);
#pragma unroll
            for (int t = 0; t < 2; t++)
#pragma unroll
                for (int j = 0; j < 8; j++)
                    mma_s8(acc_hh[t][j], a[t], &bb[j >> 1][(j & 1) * 2]);
        }
        // cross (128 bytes -> 4 mma-k steps)
#pragma unroll
        for (int ks = 0; ks < 4; ks++) {
            uint32_t a[2][4];
            ldm4(a[0][0], a[0][1], a[0][2], a[0][3], stg + OFF_AX + ax_off[0] + ks * 32);
            ldm4(a[1][0], a[1][1], a[1][2], a[1][3], stg + OFF_AX + ax_off[1] + ks * 32);
            uint32_t bb[4][4];
#pragma unroll
            for (int p = 0; p < 4; p++)
                ldm4(bb[p][0], bb[p][1], bb[p][2], bb[p][3], stg + OFF_BX + bx_off[p] + ks * 32);
#pragma unroll
            for (int t = 0; t < 2; t++)
#pragma unroll
                for (int j = 0; j < 8; j++)
                    mma_s8(acc_x[t][j], a[t], &bb[j >> 1][(j & 1) * 2]);
        }
        __syncthreads();
    }

    // ---------------- epilogue ----------------
    float sv = 0.0f, cv = 0.0f;
    if (mode == 0) {
        float ang = tptr[0] * (2.0f * 3.14159265358979323846f / 24.0f);
        sv = sinf(ang); cv = cosf(ang);
    }
    const int mrow0 = bm + warp_m + (lane >> 2);
    const int ncol0 = bn + warp_n + (lane & 3) * 2;

#pragma unroll
    for (int t = 0; t < 2; t++)
#pragma unroll
        for (int j = 0; j < 8; j++)
#pragma unroll
            for (int half = 0; half < 2; half++) {
                int m = mrow0 + t * 16 + half * 8;
#pragma unroll
                for (int e = 0; e < 2; e++) {
                    int n = ncol0 + j * 8 + e;
                    if (n >= N) continue;
                    float v = (float)acc_hh[t][j][half * 2 + e] * s_hh
                            + (float)acc_x [t][j][half * 2 + e] * s_x
                            + bias[n];
                    if (mode == 0) {
                        v += sv * W0f32[(size_t)n * (Sdim + 2) + Sdim]
                           + cv * W0f32[(size_t)n * (Sdim + 2) + Sdim + 1];
                        v = fmaxf(v, 0.0f);
                    } else if (mode == 1) {
                        v = tanhf(v);
                    } else if (mode == 2) {
                        v = tanhf(aux[(size_t)m * aux_ld + n] + v);
                    } else if (mode == 5) {
                        Cf[(size_t)m * ldc + n] += 0.1f * (v - aux[(size_t)m * aux_ld + n]);
                        continue;
                    }
                    if (Cf) Cf[(size_t)m * ldc + n] = v;
                    if (Ohi) {
                        int8_t hi, lo; quant_split(v, oinv, hi, lo);
                        Ohi[(size_t)m * ldo + n] = hi;
                        uint16_t pair = (uint16_t)(uint8_t)hi | ((uint16_t)(uint8_t)lo << 8);
                        *(uint16_t*)(Ox + ((size_t)m * ldo + n) * 2) = pair;
                    }
                }
            }
}

// ---------------- tiny local path (Z=8, E=4) ----------------
__global__ void loc_kernel(
    const float* __restrict__ state, float* __restrict__ out,
    const float* __restrict__ loc_proj_w, const float* __restrict__ loc_proj_b,
    const float* __restrict__ lp_in_w,   const float* __restrict__ lp_in_b,
    const float* __restrict__ lp_out_w,  const float* __restrict__ lp_out_b,
    const float* __restrict__ loc_back_w,const float* __restrict__ loc_back_b)
{
    int m = blockIdx.x * blockDim.x + threadIdx.x;
    if (m >= Bsz) return;
    float loc[8];
#pragma unroll
    for (int j = 0; j < 8; j++) loc[j] = state[(size_t)m * Sdim + Adim + j];
    float lp[4];
#pragma unroll
    for (int i = 0; i < 4; i++) {
        float a = loc_proj_b[i];
#pragma unroll
        for (int j = 0; j < 8; j++) a += loc_proj_w[i * 8 + j] * loc[j];
        lp[i] = a;
    }
    float v[4];
#pragma unroll
    for (int i = 0; i < 4; i++) {
        float a = lp_in_b[8 + i];
#pragma unroll
        for (int j = 0; j < 4; j++) a += lp_in_w[(8 + i) * 4 + j] * lp[j];
        v[i] = a;
    }
    float d[4];
#pragma unroll
    for (int i = 0; i < 4; i++) {
        float a = lp_out_b[i];
#pragma unroll
        for (int j = 0; j < 4; j++) a += lp_out_w[i * 4 + j] * v[j];
        d[i] = a - lp[i];
    }
#pragma unroll
    for (int i = 0; i < 8; i++) {
        float a = loc_back_b[i];
#pragma unroll
        for (int j = 0; j < 4; j++) a += loc_back_w[i * 4 + j] * d[j];
        out[(size_t)m * Sdim + Adim + i] += 0.1f * a;
    }
}

// ---------------- launch ----------------
extern "C" void kernel_launch(void* const* d_in, const int* in_sizes, int n_in,
                              void* d_out, int out_size)
{
    const float* t          = (const float*)d_in[0];
    const float* state      = (const float*)d_in[1];
    const float* W0         = (const float*)d_in[2];
    const float* b0         = (const float*)d_in[3];
    const float* res_W1     = (const float*)d_in[4];
    const float* res_b1     = (const float*)d_in[5];
    const float* res_W2     = (const float*)d_in[6];
    const float* res_b2     = (const float*)d_in[7];
    const float* Wf         = (const float*)d_in[8];
    const float* bf         = (const float*)d_in[9];
    const float* lp_in_w    = (const float*)d_in[10];
    const float* lp_in_b    = (const float*)d_in[11];
    const float* lp_out_w   = (const float*)d_in[12];
    const float* lp_out_b   = (const float*)d_in[13];
    const float* ta_in_w    = (const float*)d_in[14];
    const float* ta_in_b    = (const float*)d_in[15];
    const float* ta_out_w   = (const float*)d_in[16];
    const float* ta_out_b   = (const float*)d_in[17];
    const float* loc_proj_w = (const float*)d_in[18];
    const float* loc_proj_b = (const float*)d_in[19];
    const float* loc_back_w = (const float*)d_in[20];
    const float* loc_back_b = (const float*)d_in[21];
    float* out = (float*)d_out;

    float* h;
    int8_t *sp_hi,*sp_x,*h_hi,*h_x,*u_hi,*u_x,*v2_hi,*v2_x;
    int8_t *w0_hi,*w0_x,*rw1_hi,*rw1_x,*rw2_hi,*rw2_x,*wf_hi,*wf_x;
    int8_t *tain_hi,*tain_x,*taout_hi,*taout_x;
    cudaGetSymbolAddress((void**)&h,       g_h);
    cudaGetSymbolAddress((void**)&sp_hi,   g_sp_hi);
    cudaGetSymbolAddress((void**)&sp_x,    g_sp_x);
    cudaGetSymbolAddress((void**)&h_hi,    g_h_hi);
    cudaGetSymbolAddress((void**)&h_x,     g_h_x);
    cudaGetSymbolAddress((void**)&u_hi,    g_u_hi);
    cudaGetSymbolAddress((void**)&u_x,     g_u_x);
    cudaGetSymbolAddress((void**)&v2_hi,   g_v2_hi);
    cudaGetSymbolAddress((void**)&v2_x,    g_v2_x);
    cudaGetSymbolAddress((void**)&w0_hi,   g_w0_hi);
    cudaGetSymbolAddress((void**)&w0_x,    g_w0_x);
    cudaGetSymbolAddress((void**)&rw1_hi,  g_rw1_hi);
    cudaGetSymbolAddress((void**)&rw1_x,   g_rw1_x);
    cudaGetSymbolAddress((void**)&rw2_hi,  g_rw2_hi);
    cudaGetSymbolAddress((void**)&rw2_x,   g_rw2_x);
    cudaGetSymbolAddress((void**)&wf_hi,   g_wf_hi);
    cudaGetSymbolAddress((void**)&wf_x,    g_wf_x);
    cudaGetSymbolAddress((void**)&tain_hi, g_tain_hi);
    cudaGetSymbolAddress((void**)&tain_x,  g_tain_x);
    cudaGetSymbolAddress((void**)&taout_hi,g_taout_hi);
    cudaGetSymbolAddress((void**)&taout_x, g_taout_x);

    cudaFuncSetAttribute(s8_gemm, cudaFuncAttributeMaxDynamicSharedMemorySize, SMEM_DYN);

    // scale constants:  v = acc_hh*65536*s + acc_x*256*s,  s = Ra*Rb/QMAX^2
    const float inv_w  = QMAX / R_W;
    const float inv_st = QMAX / R_ST;
    const float q2 = QMAX * QMAX;
    const float s_st   = (R_ST   * R_W) / q2;
    const float s_relu = (R_RELU * R_W) / q2;
    const float s_tanh = (R_TANH * R_W) / q2;
    const float s_v2   = (R_V2   * R_W) / q2;
    const float oinv_relu = QMAX / R_RELU;
    const float oinv_tanh = QMAX / R_TANH;
    const float oinv_v2   = QMAX / R_V2;

    // ---- conversions ----
    {
        int tb = 256;
        conv16<<<640,  tb>>>(state, sp_hi, sp_x, Bsz, Sdim, Sdim, SPADK, 1, inv_st);
        conv16<<<80,   tb>>>(W0, w0_hi, w0_x, Hdim, Sdim + 2, Sdim, SPADK, 0, inv_w);
        conv16<<<2048, tb>>>(res_W1, rw1_hi, rw1_x, Rn * Hdim, Hdim, Hdim, Hdim, 0, inv_w);
        conv16<<<2048, tb>>>(res_W2, rw2_hi, rw2_x, Rn * Hdim, Hdim, Hdim, Hdim, 0, inv_w);
        conv16<<<67,   tb>>>(Wf, wf_hi, wf_x, Sdim, Hdim, Hdim, Hdim, 0, inv_w);
        conv16<<<16,   tb>>>(ta_in_w + (size_t)2 * Adim * Adim, tain_hi, tain_x, Adim, Adim, Adim, Adim, 0, inv_w);
        conv16<<<16,   tb>>>(ta_out_w, taout_hi, taout_x, Adim, Adim, Adim, Adim, 0, inv_w);
    }

    const int MY = Bsz / 128; // 64
    dim3 blk(256);

    // K1: h = relu(state@W0^T + time + b0) -> h f32 + h pair (range R_RELU)
    s8_gemm<<<dim3(Hdim / 128, MY), blk, SMEM_DYN>>>(
        sp_hi, sp_x, SPADK, w0_hi, w0_x, SPADK, Hdim, SPADK,
        s_st * 65536.0f, s_st * 256.0f,
        b0, nullptr, 0, h, Hdim, h_hi, h_x, Hdim, oinv_relu, 0, W0, t);

    // residual scan
    for (int r = 0; r < Rn; r++) {
        const int8_t* W1h = rw1_hi + (size_t)r * Hdim * Hdim;
        const int8_t* W1x = rw1_x  + (size_t)r * Hdim * Hdim * 2;
        const int8_t* W2h = rw2_hi + (size_t)r * Hdim * Hdim;
        const int8_t* W2x = rw2_x  + (size_t)r * Hdim * Hdim * 2;
        const float* b1 = res_b1 + (size_t)r * Hdim;
        const float* b2 = res_b2 + (size_t)r * Hdim;
        float s_u = (r == 0) ? s_relu : s_tanh;
        // u = tanh(h@W1^T + b1)
        s8_gemm<<<dim3(Hdim / 128, MY), blk, SMEM_DYN>>>(
            h_hi, h_x, Hdim, W1h, W1x, Hdim, Hdim, Hdim,
            s_u * 65536.0f, s_u * 256.0f,
            b1, nullptr, 0, nullptr, 0, u_hi, u_x, Hdim, oinv_tanh, 1, nullptr, nullptr);
        // h = tanh(h + u@W2^T + b2)
        s8_gemm<<<dim3(Hdim / 128, MY), blk, SMEM_DYN>>>(
            u_hi, u_x, Hdim, W2h, W2x, Hdim, Hdim, Hdim,
            s_tanh * 65536.0f, s_tanh * 256.0f,
            b2, h, Hdim, h, Hdim, h_hi, h_x, Hdim, oinv_tanh, 2, nullptr, nullptr);
    }

    // K4: out = h@Wf^T + bf (N=268)
    s8_gemm<<<dim3((Sdim + 127) / 128, MY), blk, SMEM_DYN>>>(
        h_hi, h_x, Hdim, wf_hi, wf_x, Hdim, Sdim, Hdim,
        s_tanh * 65536.0f, s_tanh * 256.0f,
        bf, nullptr, 0, out, Sdim, nullptr, nullptr, 0, 0.0f, 3, nullptr, nullptr);

    // K5: v2 = state[:, :256]@ta_in[512:768]^T + b
    s8_gemm<<<dim3(Adim / 128, MY), blk, SMEM_DYN>>>(
        sp_hi, sp_x, SPADK, tain_hi, tain_x, Adim, Adim, Adim,
        s_st * 65536.0f, s_st * 256.0f,
        ta_in_b + 2 * Adim, nullptr, 0, nullptr, 0, v2_hi, v2_x, Adim, oinv_v2, 3, nullptr, nullptr);

    // K6: out[:, :256] += 0.1*((v2@ta_out^T + b) - state[:, :256])
    s8_gemm<<<dim3(Adim / 128, MY), blk, SMEM_DYN>>>(
        v2_hi, v2_x, Adim, taout_hi, taout_x, Adim, Adim, Adim,
        s_v2 * 65536.0f, s_v2 * 256.0f,
        ta_out_b, state, Sdim, out, Sdim, nullptr, nullptr, 0, 0.0f, 5, nullptr, nullptr);

    // K7: loc path
    loc_kernel<<<Bsz / 256, 256>>>(state, out,
                                   loc_proj_w, loc_proj_b,
                                   lp_in_w, lp_in_b,
                                   lp_out_w, lp_out_b,
                                   loc_back_w, loc_back_b);
}

// round 11
// speedup vs baseline: 1.3474x; 1.3474x over previous
#include <cuda_runtime.h>
#include <cuda_bf16.h>
#include <cstdint>
#include <math.h>

// ---------------- problem constants ----------------
#define Bsz 8192
#define Sdim 268
#define Hdim 1024
#define Rn 8
#define Adim 256
#define SPADK 320           // state/W0 logical K padded to mult of 64

// Triple-K sizes (K' = 3*K logical)
#define KP_S   960
#define KP_H   3072
#define KP_A   768

// ---------------- device scratch (allocation-free) ----------------
__device__ float         g_h[(size_t)Bsz * Hdim];
__device__ __nv_bfloat16 g_sp3[(size_t)Bsz * KP_S];
__device__ __nv_bfloat16 g_h3[(size_t)Bsz * KP_H];
__device__ __nv_bfloat16 g_u3[(size_t)Bsz * KP_H];
__device__ __nv_bfloat16 g_v23[(size_t)Bsz * KP_A];
__device__ __nv_bfloat16 g_w03[(size_t)Hdim * KP_S];
__device__ __nv_bfloat16 g_rw13[(size_t)Rn * Hdim * KP_H];
__device__ __nv_bfloat16 g_rw23[(size_t)Rn * Hdim * KP_H];
__device__ __nv_bfloat16 g_wf3[(size_t)Sdim * KP_H];
__device__ __nv_bfloat16 g_tain3[(size_t)Adim * KP_A];
__device__ __nv_bfloat16 g_taout3[(size_t)Adim * KP_A];

// ---------------- helpers ----------------
__device__ __forceinline__ void split_bf16(float x, __nv_bfloat16& hi, __nv_bfloat16& lo) {
    hi = __float2bfloat16(x);
    lo = __float2bfloat16(x - __bfloat162float(hi));
}
__device__ __forceinline__ uint32_t smem_u32(const void* p) {
    uint32_t a;
    asm("{ .reg .u64 t; cvta.to.shared.u64 t, %1; cvt.u32.u64 %0, t; }" : "=r"(a) : "l"(p));
    return a;
}
__device__ __forceinline__ void cp16(uint32_t dst, const void* src, uint32_t sz) {
    asm volatile("cp.async.cg.shared.global [%0], [%1], 16, %2;"
                 :: "r"(dst), "l"(src), "r"(sz) : "memory");
}
__device__ __forceinline__ void ldm4(uint32_t& r0, uint32_t& r1, uint32_t& r2, uint32_t& r3, uint32_t a) {
    asm volatile("ldmatrix.sync.aligned.m8n8.x4.shared.b16 {%0,%1,%2,%3}, [%4];"
                 : "=r"(r0), "=r"(r1), "=r"(r2), "=r"(r3) : "r"(a));
}
__device__ __forceinline__ void mma16816(float* d, const uint32_t* a, const uint32_t* b) {
    asm volatile("mma.sync.aligned.m16n8k16.row.col.f32.bf16.bf16.f32 "
                 "{%0,%1,%2,%3}, {%4,%5,%6,%7}, {%8,%9}, {%0,%1,%2,%3};"
                 : "+f"(d[0]), "+f"(d[1]), "+f"(d[2]), "+f"(d[3])
                 : "r"(a[0]), "r"(a[1]), "r"(a[2]), "r"(a[3]), "r"(b[0]), "r"(b[1]));
}

// ---------------- vectorized conversion: 8 logical k per thread ----------------
// aSide=1: [hi,hi,lo]   aSide=0: [hi,lo,hi]
__global__ void conv8(const float* __restrict__ src, __nv_bfloat16* __restrict__ dst,
                      int rows, int src_ld, int src_cols, int Klog, int aSide)
{
    const int per = Klog >> 3;
    size_t n = (size_t)rows * per;
    size_t stride = (size_t)gridDim.x * blockDim.x;
    for (size_t i = (size_t)blockIdx.x * blockDim.x + threadIdx.x; i < n; i += stride) {
        int r = (int)(i / per);
        int k0 = (int)(i % per) * 8;
        const float* s = src + (size_t)r * src_ld + k0;
        __nv_bfloat16 o[24];
#pragma unroll
        for (int j = 0; j < 8; j++) {
            int k = k0 + j;
            float x = (k < src_cols) ? s[j] : 0.0f;
            __nv_bfloat16 hi, lo; split_bf16(x, hi, lo);
            if (aSide) { o[j*3] = hi; o[j*3+1] = hi; o[j*3+2] = lo; }
            else       { o[j*3] = hi; o[j*3+1] = lo; o[j*3+2] = hi; }
        }
        uint4* d = (uint4*)(dst + ((size_t)r * Klog + k0) * 3);
        const uint4* ov = (const uint4*)o;
        d[0] = ov[0]; d[1] = ov[1]; d[2] = ov[2];
    }
}

// ---------------- HMMA GEMM: C(MxN) = A'(MxK') * B'(NxK')^T ----------------
// CTA 128x128, KC=64, 2-stage cp.async double buffer, 8 warps of 32x64.
// modes: 0 relu(D+time+bias) -> Cf + triple
//        1 tanh(D+bias)      -> triple only
//        2 tanh(aux+D+bias)  -> Cf + triple
//        3 D+bias            -> Cf (and triple if given)
//        5 Cf += 0.1*(D+bias - aux)
#define KC 64
#define ROWB 144
#define TILEB (128 * ROWB)
#define STAGEB (2 * TILEB)         // 36864
#define SMEM_DYN (2 * STAGEB)      // 73728

__global__ __launch_bounds__(256)
void hmma_gemm(const __nv_bfloat16* __restrict__ Aq, int lda,
               const __nv_bfloat16* __restrict__ Bq, int ldb,
               int N, int Kp,
               const float* __restrict__ bias,
               const float* __restrict__ aux, int aux_ld,
               float* __restrict__ Cf, int ldc,
               __nv_bfloat16* __restrict__ O3, int ldo,
               int mode,
               const float* __restrict__ W0f32, const float* __restrict__ tptr)
{
    extern __shared__ char smem[];
    const uint32_t sbase = smem_u32(smem);
    const int tid = threadIdx.x;
    const int lane = tid & 31, wid = tid >> 5;
    const int bm = blockIdx.y * 128;
    const int bn = blockIdx.x * 128;
    const int warp_m = (wid & 3) * 32;
    const int warp_n = (wid >> 2) * 64;

    uint32_t a_off[2], b_off[4];
#pragma unroll
    for (int t = 0; t < 2; t++)
        a_off[t] = (uint32_t)(warp_m + t * 16 + (lane & 15)) * ROWB + (uint32_t)(lane >> 4) * 16;
#pragma unroll
    for (int p = 0; p < 4; p++)
        b_off[p] = (uint32_t)(warp_n + p * 16 + ((lane >> 4) << 3) + (lane & 7)) * ROWB
                 + (uint32_t)((lane >> 3) & 1) * 16;

    float acc[2][8][4];
#pragma unroll
    for (int t = 0; t < 2; t++)
#pragma unroll
        for (int j = 0; j < 8; j++)
#pragma unroll
            for (int e = 0; e < 4; e++) acc[t][j][e] = 0.0f;

    const int nch = Kp / KC;
    const int lrow = tid >> 3;
    const int lkv = tid & 7;

#define ISSUE_LOADS(cc) do {                                                        \
        const int k0 = (cc) * KC;                                                   \
        const uint32_t stg = sbase + ((cc) & 1) * STAGEB;                           \
        _Pragma("unroll")                                                           \
        for (int j = 0; j < 4; j++) {                                               \
            int row = lrow + j * 32;                                                \
            uint32_t d = stg + (uint32_t)row * ROWB + (uint32_t)lkv * 16;           \
            const __nv_bfloat16* s = Aq + (size_t)(bm + row) * lda + k0 + lkv * 8;  \
            cp16(d, s, 16);                                                         \
        }                                                                           \
        _Pragma("unroll")                                                           \
        for (int j = 0; j < 4; j++) {                                               \
            int row = lrow + j * 32;                                                \
            int n0 = bn + row;                                                      \
            int nc = n0 < N ? n0 : (N - 1);                                         \
            uint32_t d = stg + TILEB + (uint32_t)row * ROWB + (uint32_t)lkv * 16;   \
            const __nv_bfloat16* s = Bq + (size_t)nc * ldb + k0 + lkv * 8;          \
            cp16(d, s, n0 < N ? 16u : 0u);                                          \
        }                                                                           \
        asm volatile("cp.async.commit_group;" ::: "memory");                        \
    } while (0)

    ISSUE_LOADS(0);

    for (int c = 0; c < nch; c++) {
        if (c + 1 < nch) {
            ISSUE_LOADS(c + 1);
            asm volatile("cp.async.wait_group 1;" ::: "memory");
        } else {
            asm volatile("cp.async.wait_group 0;" ::: "memory");
        }
        __syncthreads();

        const uint32_t sA = sbase + (c & 1) * STAGEB;
        const uint32_t sB = sA + TILEB;
#pragma unroll
        for (int ks = 0; ks < 4; ks++) {
            uint32_t a[2][4];
            ldm4(a[0][0], a[0][1], a[0][2], a[0][3], sA + a_off[0] + ks * 32);
            ldm4(a[1][0], a[1][1], a[1][2], a[1][3], sA + a_off[1] + ks * 32);
            uint32_t bb[4][4];
#pragma unroll
            for (int p = 0; p < 4; p++)
                ldm4(bb[p][0], bb[p][1], bb[p][2], bb[p][3], sB + b_off[p] + ks * 32);
#pragma unroll
            for (int t = 0; t < 2; t++)
#pragma unroll
                for (int j = 0; j < 8; j++)
                    mma16816(acc[t][j], a[t], &bb[j >> 1][(j & 1) * 2]);
        }
        __syncthreads();
    }

    // ---------------- epilogue ----------------
    float sv = 0.0f, cv = 0.0f;
    if (mode == 0) {
        float ang = tptr[0] * (2.0f * 3.14159265358979323846f / 24.0f);
        sv = sinf(ang); cv = cosf(ang);
    }
    const int mrow0 = bm + warp_m + (lane >> 2);
    const int ncol0 = bn + warp_n + (lane & 3) * 2;

#pragma unroll
    for (int t = 0; t < 2; t++)
#pragma unroll
        for (int j = 0; j < 8; j++)
#pragma unroll
            for (int half = 0; half < 2; half++) {
                int m = mrow0 + t * 16 + half * 8;
#pragma unroll
                for (int e = 0; e < 2; e++) {
                    int n = ncol0 + j * 8 + e;
                    if (n >= N) continue;
                    float v = acc[t][j][half * 2 + e] + bias[n];
                    if (mode == 0) {
                        v += sv * W0f32[(size_t)n * (Sdim + 2) + Sdim]
                           + cv * W0f32[(size_t)n * (Sdim + 2) + Sdim + 1];
                        v = fmaxf(v, 0.0f);
                    } else if (mode == 1) {
                        v = tanhf(v);
                    } else if (mode == 2) {
                        v = tanhf(aux[(size_t)m * aux_ld + n] + v);
                    } else if (mode == 5) {
                        Cf[(size_t)m * ldc + n] += 0.1f * (v - aux[(size_t)m * aux_ld + n]);
                        continue;
                    }
                    if (Cf) Cf[(size_t)m * ldc + n] = v;
                    if (O3) {
                        __nv_bfloat16 hi, lo; split_bf16(v, hi, lo);
                        size_t base = ((size_t)m * ldo + n) * 3;
                        O3[base] = hi; O3[base + 1] = hi; O3[base + 2] = lo;
                    }
                }
            }
}

// ---------------- tiny local path (Z=8, E=4) ----------------
__global__ void loc_kernel(
    const float* __restrict__ state, float* __restrict__ out,
    const float* __restrict__ loc_proj_w, const float* __restrict__ loc_proj_b,
    const float* __restrict__ lp_in_w,   const float* __restrict__ lp_in_b,
    const float* __restrict__ lp_out_w,  const float* __restrict__ lp_out_b,
    const float* __restrict__ loc_back_w,const float* __restrict__ loc_back_b)
{
    int m = blockIdx.x * blockDim.x + threadIdx.x;
    if (m >= Bsz) return;
    float loc[8];
#pragma unroll
    for (int j = 0; j < 8; j++) loc[j] = state[(size_t)m * Sdim + Adim + j];
    float lp[4];
#pragma unroll
    for (int i = 0; i < 4; i++) {
        float a = loc_proj_b[i];
#pragma unroll
        for (int j = 0; j < 8; j++) a += loc_proj_w[i * 8 + j] * loc[j];
        lp[i] = a;
    }
    float v[4];
#pragma unroll
    for (int i = 0; i < 4; i++) {
        float a = lp_in_b[8 + i];
#pragma unroll
        for (int j = 0; j < 4; j++) a += lp_in_w[(8 + i) * 4 + j] * lp[j];
        v[i] = a;
    }
    float d[4];
#pragma unroll
    for (int i = 0; i < 4; i++) {
        float a = lp_out_b[i];
#pragma unroll
        for (int j = 0; j < 4; j++) a += lp_out_w[i * 4 + j] * v[j];
        d[i] = a - lp[i];
    }
#pragma unroll
    for (int i = 0; i < 8; i++) {
        float a = loc_back_b[i];
#pragma unroll
        for (int j = 0; j < 4; j++) a += loc_back_w[i * 4 + j] * d[j];
        out[(size_t)m * Sdim + Adim + i] += 0.1f * a;
    }
}

// ---------------- launch ----------------
extern "C" void kernel_launch(void* const* d_in, const int* in_sizes, int n_in,
                              void* d_out, int out_size)
{
    const float* t          = (const float*)d_in[0];
    const float* state      = (const float*)d_in[1];
    const float* W0         = (const float*)d_in[2];
    const float* b0         = (const float*)d_in[3];
    const float* res_W1     = (const float*)d_in[4];
    const float* res_b1     = (const float*)d_in[5];
    const float* res_W2     = (const float*)d_in[6];
    const float* res_b2     = (const float*)d_in[7];
    const float* Wf         = (const float*)d_in[8];
    const float* bf         = (const float*)d_in[9];
    const float* lp_in_w    = (const float*)d_in[10];
    const float* lp_in_b    = (const float*)d_in[11];
    const float* lp_out_w   = (const float*)d_in[12];
    const float* lp_out_b   = (const float*)d_in[13];
    const float* ta_in_w    = (const float*)d_in[14];
    const float* ta_in_b    = (const float*)d_in[15];
    const float* ta_out_w   = (const float*)d_in[16];
    const float* ta_out_b   = (const float*)d_in[17];
    const float* loc_proj_w = (const float*)d_in[18];
    const float* loc_proj_b = (const float*)d_in[19];
    const float* loc_back_w = (const float*)d_in[20];
    const float* loc_back_b = (const float*)d_in[21];
    float* out = (float*)d_out;

    float* h;
    __nv_bfloat16 *sp3, *h3, *u3, *v23, *w03, *rw13, *rw23, *wf3, *tain3, *taout3;
    cudaGetSymbolAddress((void**)&h,      g_h);
    cudaGetSymbolAddress((void**)&sp3,    g_sp3);
    cudaGetSymbolAddress((void**)&h3,     g_h3);
    cudaGetSymbolAddress((void**)&u3,     g_u3);
    cudaGetSymbolAddress((void**)&v23,    g_v23);
    cudaGetSymbolAddress((void**)&w03,    g_w03);
    cudaGetSymbolAddress((void**)&rw13,   g_rw13);
    cudaGetSymbolAddress((void**)&rw23,   g_rw23);
    cudaGetSymbolAddress((void**)&wf3,    g_wf3);
    cudaGetSymbolAddress((void**)&tain3,  g_tain3);
    cudaGetSymbolAddress((void**)&taout3, g_taout3);

    cudaFuncSetAttribute(hmma_gemm, cudaFuncAttributeMaxDynamicSharedMemorySize, SMEM_DYN);

    const int MY = Bsz / 128; // 64
    dim3 blk(256);
    int tb = 256;

    // ---- conversions needed for K1 + residual scan (launches 0..3) ----
    conv8<<<1280, tb>>>(state, sp3, Bsz, Sdim, Sdim, SPADK, 1);          // launch 0
    conv8<<<160,  tb>>>(W0, w03, Hdim, Sdim + 2, Sdim, SPADK, 0);        // launch 1
    conv8<<<2048, tb>>>(res_W1, rw13, Rn * Hdim, Hdim, Hdim, Hdim, 0);   // launch 2
    conv8<<<2048, tb>>>(res_W2, rw23, Rn * Hdim, Hdim, Hdim, Hdim, 0);   // launch 3

    // K1 (launch 4): h = relu(state@W0^T + time + b0) -> h f32 + h3 triple
    hmma_gemm<<<dim3(Hdim / 128, MY), blk, SMEM_DYN>>>(
        sp3, KP_S, w03, KP_S, Hdim, KP_S,
        b0, nullptr, 0, h, Hdim, h3, Hdim, 0, W0, t);

    // residual scan (launch 5 = first u-GEMM -> ncu -s 5 -c 1 captures THIS)
    for (int r = 0; r < Rn; r++) {
        const __nv_bfloat16* W13 = rw13 + (size_t)r * Hdim * KP_H;
        const __nv_bfloat16* W23 = rw23 + (size_t)r * Hdim * KP_H;
        const float* b1 = res_b1 + (size_t)r * Hdim;
        const float* b2 = res_b2 + (size_t)r * Hdim;
        hmma_gemm<<<dim3(Hdim / 128, MY), blk, SMEM_DYN>>>(
            h3, KP_H, W13, KP_H, Hdim, KP_H,
            b1, nullptr, 0, nullptr, 0, u3, Hdim, 1, nullptr, nullptr);
        hmma_gemm<<<dim3(Hdim / 128, MY), blk, SMEM_DYN>>>(
            u3, KP_H, W23, KP_H, Hdim, KP_H,
            b2, h, Hdim, h, Hdim, h3, Hdim, 2, nullptr, nullptr);
    }

    // ---- conversions for the tail GEMMs (only needed from here on) ----
    conv8<<<136, tb>>>(Wf, wf3, Sdim, Hdim, Hdim, Hdim, 0);
    conv8<<<32,  tb>>>(ta_in_w + (size_t)2 * Adim * Adim, tain3, Adim, Adim, Adim, Adim, 0);
    conv8<<<32,  tb>>>(ta_out_w, taout3, Adim, Adim, Adim, Adim, 0);

    // K4: out = h@Wf^T + bf (N=268)
    hmma_gemm<<<dim3((Sdim + 127) / 128, MY), blk, SMEM_DYN>>>(
        h3, KP_H, wf3, KP_H, Sdim, KP_H,
        bf, nullptr, 0, out, Sdim, nullptr, 0, 3, nullptr, nullptr);

    // K5: v2 = state[:, :256]@ta_in[512:768]^T + b -> v23
    hmma_gemm<<<dim3(Adim / 128, MY), blk, SMEM_DYN>>>(
        sp3, KP_S, tain3, KP_A, Adim, KP_A,
        ta_in_b + 2 * Adim, nullptr, 0, nullptr, 0, v23, Adim, 3, nullptr, nullptr);

    // K6: out[:, :256] += 0.1*((v2@ta_out^T + b) - state[:, :256])
    hmma_gemm<<<dim3(Adim / 128, MY), blk, SMEM_DYN>>>(
        v23, KP_A, taout3, KP_A, Adim, KP_A,
        ta_out_b, state, Sdim, out, Sdim, nullptr, 0, 5, nullptr, nullptr);

    // K7: loc path
    loc_kernel<<<Bsz / 256, 256>>>(state, out,
                                   loc_proj_w, loc_proj_b,
                                   lp_in_w, lp_in_b,
                                   lp_out_w, lp_out_b,
                                   loc_back_w, loc_back_b);
}

// round 12
// speedup vs baseline: 2.0805x; 1.5441x over previous
#include <cuda_runtime.h>
#include <cuda_bf16.h>
#include <cstdint>
#include <math.h>

// ---------------- problem constants ----------------
#define Bsz 8192
#define Sdim 268
#define Hdim 1024
#define Rn 8
#define Adim 256
#define SPADK 320           // state/W0 logical K padded to mult of 64

// Triple-K sizes (K' = 3*K logical)
#define KP_S   960
#define KP_H   3072
#define KP_A   768

// ---------------- device scratch (allocation-free) ----------------
__device__ float         g_h[(size_t)Bsz * Hdim];
__device__ __nv_bfloat16 g_sp3[(size_t)Bsz * KP_S];
__device__ __nv_bfloat16 g_h3[(size_t)Bsz * KP_H];
__device__ __nv_bfloat16 g_u3[(size_t)Bsz * KP_H];
__device__ __nv_bfloat16 g_v23[(size_t)Bsz * KP_A];
__device__ __nv_bfloat16 g_w03[(size_t)Hdim * KP_S];
__device__ __nv_bfloat16 g_rw13[(size_t)Rn * Hdim * KP_H];
__device__ __nv_bfloat16 g_rw23[(size_t)Rn * Hdim * KP_H];
__device__ __nv_bfloat16 g_wf3[(size_t)Sdim * KP_H];
__device__ __nv_bfloat16 g_tain3[(size_t)Adim * KP_A];
__device__ __nv_bfloat16 g_taout3[(size_t)Adim * KP_A];

// ---------------- helpers ----------------
__device__ __forceinline__ void split_bf16(float x, __nv_bfloat16& hi, __nv_bfloat16& lo) {
    hi = __float2bfloat16(x);
    lo = __float2bfloat16(x - __bfloat162float(hi));
}
__device__ __forceinline__ uint32_t smem_u32(const void* p) {
    uint32_t a;
    asm("{ .reg .u64 t; cvta.to.shared.u64 t, %1; cvt.u32.u64 %0, t; }" : "=r"(a) : "l"(p));
    return a;
}
__device__ __forceinline__ void cp16(uint32_t dst, const void* src, uint32_t sz) {
    asm volatile("cp.async.cg.shared.global [%0], [%1], 16, %2;"
                 :: "r"(dst), "l"(src), "r"(sz) : "memory");
}
__device__ __forceinline__ void ldm4(uint32_t& r0, uint32_t& r1, uint32_t& r2, uint32_t& r3, uint32_t a) {
    asm volatile("ldmatrix.sync.aligned.m8n8.x4.shared.b16 {%0,%1,%2,%3}, [%4];"
                 : "=r"(r0), "=r"(r1), "=r"(r2), "=r"(r3) : "r"(a));
}
__device__ __forceinline__ void mma16816(float* d, const uint32_t* a, const uint32_t* b) {
    asm volatile("mma.sync.aligned.m16n8k16.row.col.f32.bf16.bf16.f32 "
                 "{%0,%1,%2,%3}, {%4,%5,%6,%7}, {%8,%9}, {%0,%1,%2,%3};"
                 : "+f"(d[0]), "+f"(d[1]), "+f"(d[2]), "+f"(d[3])
                 : "r"(a[0]), "r"(a[1]), "r"(a[2]), "r"(a[3]), "r"(b[0]), "r"(b[1]));
}

// ---------------- vectorized conversion: 8 logical k per thread ----------------
// aSide=1: [hi,hi,lo]   aSide=0: [hi,lo,hi]
__global__ void conv8(const float* __restrict__ src, __nv_bfloat16* __restrict__ dst,
                      int rows, int src_ld, int src_cols, int Klog, int aSide)
{
    const int per = Klog >> 3;
    size_t n = (size_t)rows * per;
    size_t stride = (size_t)gridDim.x * blockDim.x;
    for (size_t i = (size_t)blockIdx.x * blockDim.x + threadIdx.x; i < n; i += stride) {
        int r = (int)(i / per);
        int k0 = (int)(i % per) * 8;
        const float* s = src + (size_t)r * src_ld + k0;
        __nv_bfloat16 o[24];
#pragma unroll
        for (int j = 0; j < 8; j++) {
            int k = k0 + j;
            float x = (k < src_cols) ? s[j] : 0.0f;
            __nv_bfloat16 hi, lo; split_bf16(x, hi, lo);
            if (aSide) { o[j*3] = hi; o[j*3+1] = hi; o[j*3+2] = lo; }
            else       { o[j*3] = hi; o[j*3+1] = lo; o[j*3+2] = hi; }
        }
        uint4* d = (uint4*)(dst + ((size_t)r * Klog + k0) * 3);
        const uint4* ov = (const uint4*)o;
        d[0] = ov[0]; d[1] = ov[1]; d[2] = ov[2];
    }
}

// ---------------- HMMA GEMM: C(MxN) = A'(MxK') * B'(NxK')^T ----------------
// CTA 128x128, KC=64, 2-stage cp.async double buffer, 8 warps of 32x64.
// modes: 0 relu(D+time+bias) -> Cf + triple
//        1 tanh(D+bias)      -> triple only
//        2 tanh(aux+D+bias)  -> Cf + triple
//        3 D+bias            -> Cf (and triple if given)
//        5 Cf += 0.1*(D+bias - aux)
#define KC 64
#define ROWB 144
#define TILEB (128 * ROWB)
#define STAGEB (2 * TILEB)         // 36864
#define SMEM_DYN (2 * STAGEB)      // 73728

__global__ __launch_bounds__(256)
void hmma_gemm(const __nv_bfloat16* __restrict__ Aq, int lda,
               const __nv_bfloat16* __restrict__ Bq, int ldb,
               int N, int Kp,
               const float* __restrict__ bias,
               const float* __restrict__ aux, int aux_ld,
               float* __restrict__ Cf, int ldc,
               __nv_bfloat16* __restrict__ O3, int ldo,
               int mode,
               const float* __restrict__ W0f32, const float* __restrict__ tptr)
{
    extern __shared__ char smem[];
    const uint32_t sbase = smem_u32(smem);
    const int tid = threadIdx.x;
    const int lane = tid & 31, wid = tid >> 5;
    const int bm = blockIdx.y * 128;
    const int bn = blockIdx.x * 128;
    const int warp_m = (wid & 3) * 32;
    const int warp_n = (wid >> 2) * 64;

    uint32_t a_off[2], b_off[4];
#pragma unroll
    for (int t = 0; t < 2; t++)
        a_off[t] = (uint32_t)(warp_m + t * 16 + (lane & 15)) * ROWB + (uint32_t)(lane >> 4) * 16;
#pragma unroll
    for (int p = 0; p < 4; p++)
        b_off[p] = (uint32_t)(warp_n + p * 16 + ((lane >> 4) << 3) + (lane & 7)) * ROWB
                 + (uint32_t)((lane >> 3) & 1) * 16;

    float acc[2][8][4];
#pragma unroll
    for (int t = 0; t < 2; t++)
#pragma unroll
        for (int j = 0; j < 8; j++)
#pragma unroll
            for (int e = 0; e < 4; e++) acc[t][j][e] = 0.0f;

    const int nch = Kp / KC;
    const int lrow = tid >> 3;
    const int lkv = tid & 7;

#define ISSUE_LOADS(cc) do {                                                        \
        const int k0 = (cc) * KC;                                                   \
        const uint32_t stg = sbase + ((cc) & 1) * STAGEB;                           \
        _Pragma("unroll")                                                           \
        for (int j = 0; j < 4; j++) {                                               \
            int row = lrow + j * 32;                                                \
            uint32_t d = stg + (uint32_t)row * ROWB + (uint32_t)lkv * 16;           \
            const __nv_bfloat16* s = Aq + (size_t)(bm + row) * lda + k0 + lkv * 8;  \
            cp16(d, s, 16);                                                         \
        }                                                                           \
        _Pragma("unroll")                                                           \
        for (int j = 0; j < 4; j++) {                                               \
            int row = lrow + j * 32;                                                \
            int n0 = bn + row;                                                      \
            int nc = n0 < N ? n0 : (N - 1);                                         \
            uint32_t d = stg + TILEB + (uint32_t)row * ROWB + (uint32_t)lkv * 16;   \
            const __nv_bfloat16* s = Bq + (size_t)nc * ldb + k0 + lkv * 8;          \
            cp16(d, s, n0 < N ? 16u : 0u);                                          \
        }                                                                           \
        asm volatile("cp.async.commit_group;" ::: "memory");                        \
    } while (0)

    ISSUE_LOADS(0);

    for (int c = 0; c < nch; c++) {
        if (c + 1 < nch) {
            ISSUE_LOADS(c + 1);
            asm volatile("cp.async.wait_group 1;" ::: "memory");
        } else {
            asm volatile("cp.async.wait_group 0;" ::: "memory");
        }
        __syncthreads();

        const uint32_t sA = sbase + (c & 1) * STAGEB;
        const uint32_t sB = sA + TILEB;
#pragma unroll
        for (int ks = 0; ks < 4; ks++) {
            uint32_t a[2][4];
            ldm4(a[0][0], a[0][1], a[0][2], a[0][3], sA + a_off[0] + ks * 32);
            ldm4(a[1][0], a[1][1], a[1][2], a[1][3], sA + a_off[1] + ks * 32);
            uint32_t bb[4][4];
#pragma unroll
            for (int p = 0; p < 4; p++)
                ldm4(bb[p][0], bb[p][1], bb[p][2], bb[p][3], sB + b_off[p] + ks * 32);
#pragma unroll
            for (int t = 0; t < 2; t++)
#pragma unroll
                for (int j = 0; j < 8; j++)
                    mma16816(acc[t][j], a[t], &bb[j >> 1][(j & 1) * 2]);
        }
        __syncthreads();
    }

    // ---------------- epilogue ----------------
    float sv = 0.0f, cv = 0.0f;
    if (mode == 0) {
        float ang = tptr[0] * (2.0f * 3.14159265358979323846f / 24.0f);
        sv = sinf(ang); cv = cosf(ang);
    }
    const int mrow0 = bm + warp_m + (lane >> 2);
    const int ncol0 = bn + warp_n + (lane & 3) * 2;

#pragma unroll
    for (int t = 0; t < 2; t++)
#pragma unroll
        for (int j = 0; j < 8; j++)
#pragma unroll
            for (int half = 0; half < 2; half++) {
                int m = mrow0 + t * 16 + half * 8;
#pragma unroll
                for (int e = 0; e < 2; e++) {
                    int n = ncol0 + j * 8 + e;
                    if (n >= N) continue;
                    float v = acc[t][j][half * 2 + e] + bias[n];
                    if (mode == 0) {
                        v += sv * W0f32[(size_t)n * (Sdim + 2) + Sdim]
                           + cv * W0f32[(size_t)n * (Sdim + 2) + Sdim + 1];
                        v = fmaxf(v, 0.0f);
                    } else if (mode == 1) {
                        v = tanhf(v);
                    } else if (mode == 2) {
                        v = tanhf(aux[(size_t)m * aux_ld + n] + v);
                    } else if (mode == 5) {
                        Cf[(size_t)m * ldc + n] += 0.1f * (v - aux[(size_t)m * aux_ld + n]);
                        continue;
                    }
                    if (Cf) Cf[(size_t)m * ldc + n] = v;
                    if (O3) {
                        __nv_bfloat16 hi, lo; split_bf16(v, hi, lo);
                        size_t base = ((size_t)m * ldo + n) * 3;
                        O3[base] = hi; O3[base + 1] = hi; O3[base + 2] = lo;
                    }
                }
            }
}

// ---------------- tiny local path (Z=8, E=4) ----------------
__global__ void loc_kernel(
    const float* __restrict__ state, float* __restrict__ out,
    const float* __restrict__ loc_proj_w, const float* __restrict__ loc_proj_b,
    const float* __restrict__ lp_in_w,   const float* __restrict__ lp_in_b,
    const float* __restrict__ lp_out_w,  const float* __restrict__ lp_out_b,
    const float* __restrict__ loc_back_w,const float* __restrict__ loc_back_b)
{
    int m = blockIdx.x * blockDim.x + threadIdx.x;
    if (m >= Bsz) return;
    float loc[8];
#pragma unroll
    for (int j = 0; j < 8; j++) loc[j] = state[(size_t)m * Sdim + Adim + j];
    float lp[4];
#pragma unroll
    for (int i = 0; i < 4; i++) {
        float a = loc_proj_b[i];
#pragma unroll
        for (int j = 0; j < 8; j++) a += loc_proj_w[i * 8 + j] * loc[j];
        lp[i] = a;
    }
    float v[4];
#pragma unroll
    for (int i = 0; i < 4; i++) {
        float a = lp_in_b[8 + i];
#pragma unroll
        for (int j = 0; j < 4; j++) a += lp_in_w[(8 + i) * 4 + j] * lp[j];
        v[i] = a;
    }
    float d[4];
#pragma unroll
    for (int i = 0; i < 4; i++) {
        float a = lp_out_b[i];
#pragma unroll
        for (int j = 0; j < 4; j++) a += lp_out_w[i * 4 + j] * v[j];
        d[i] = a - lp[i];
    }
#pragma unroll
    for (int i = 0; i < 8; i++) {
        float a = loc_back_b[i];
#pragma unroll
        for (int j = 0; j < 4; j++) a += loc_back_w[i * 4 + j] * d[j];
        out[(size_t)m * Sdim + Adim + i] += 0.1f * a;
    }
}

// ---------------- launch ----------------
extern "C" void kernel_launch(void* const* d_in, const int* in_sizes, int n_in,
                              void* d_out, int out_size)
{
    const float* t          = (const float*)d_in[0];
    const float* state      = (const float*)d_in[1];
    const float* W0         = (const float*)d_in[2];
    const float* b0         = (const float*)d_in[3];
    const float* res_W1     = (const float*)d_in[4];
    const float* res_b1     = (const float*)d_in[5];
    const float* res_W2     = (const float*)d_in[6];
    const float* res_b2     = (const float*)d_in[7];
    const float* Wf         = (const float*)d_in[8];
    const float* bf         = (const float*)d_in[9];
    const float* lp_in_w    = (const float*)d_in[10];
    const float* lp_in_b    = (const float*)d_in[11];
    const float* lp_out_w   = (const float*)d_in[12];
    const float* lp_out_b   = (const float*)d_in[13];
    const float* ta_in_w    = (const float*)d_in[14];
    const float* ta_in_b    = (const float*)d_in[15];
    const float* ta_out_w   = (const float*)d_in[16];
    const float* ta_out_b   = (const float*)d_in[17];
    const float* loc_proj_w = (const float*)d_in[18];
    const float* loc_proj_b = (const float*)d_in[19];
    const float* loc_back_w = (const float*)d_in[20];
    const float* loc_back_b = (const float*)d_in[21];
    float* out = (float*)d_out;

    float* h;
    __nv_bfloat16 *sp3, *h3, *u3, *v23, *w03, *rw13, *rw23, *wf3, *tain3, *taout3;
    cudaGetSymbolAddress((void**)&h,      g_h);
    cudaGetSymbolAddress((void**)&sp3,    g_sp3);
    cudaGetSymbolAddress((void**)&h3,     g_h3);
    cudaGetSymbolAddress((void**)&u3,     g_u3);
    cudaGetSymbolAddress((void**)&v23,    g_v23);
    cudaGetSymbolAddress((void**)&w03,    g_w03);
    cudaGetSymbolAddress((void**)&rw13,   g_rw13);
    cudaGetSymbolAddress((void**)&rw23,   g_rw23);
    cudaGetSymbolAddress((void**)&wf3,    g_wf3);
    cudaGetSymbolAddress((void**)&tain3,  g_tain3);
    cudaGetSymbolAddress((void**)&taout3, g_taout3);

    cudaFuncSetAttribute(hmma_gemm, cudaFuncAttributeMaxDynamicSharedMemorySize, SMEM_DYN);

    const int MY = Bsz / 128; // 64
    dim3 blk(256);
    int tb = 256;

    // ---- conversions (all upfront, R4 order) ----
    conv8<<<1280, tb>>>(state, sp3, Bsz, Sdim, Sdim, SPADK, 1);
    conv8<<<160,  tb>>>(W0, w03, Hdim, Sdim + 2, Sdim, SPADK, 0);
    conv8<<<2048, tb>>>(res_W1, rw13, Rn * Hdim, Hdim, Hdim, Hdim, 0);
    conv8<<<2048, tb>>>(res_W2, rw23, Rn * Hdim, Hdim, Hdim, Hdim, 0);
    conv8<<<136,  tb>>>(Wf, wf3, Sdim, Hdim, Hdim, Hdim, 0);
    conv8<<<32,   tb>>>(ta_in_w + (size_t)2 * Adim * Adim, tain3, Adim, Adim, Adim, Adim, 0);
    conv8<<<32,   tb>>>(ta_out_w, taout3, Adim, Adim, Adim, Adim, 0);

    // K1: h = relu(state@W0^T + time + b0) -> h f32 + h3 triple
    hmma_gemm<<<dim3(Hdim / 128, MY), blk, SMEM_DYN>>>(
        sp3, KP_S, w03, KP_S, Hdim, KP_S,
        b0, nullptr, 0, h, Hdim, h3, Hdim, 0, W0, t);

    // residual scan
    for (int r = 0; r < Rn; r++) {
        const __nv_bfloat16* W13 = rw13 + (size_t)r * Hdim * KP_H;
        const __nv_bfloat16* W23 = rw23 + (size_t)r * Hdim * KP_H;
        const float* b1 = res_b1 + (size_t)r * Hdim;
        const float* b2 = res_b2 + (size_t)r * Hdim;
        hmma_gemm<<<dim3(Hdim / 128, MY), blk, SMEM_DYN>>>(
            h3, KP_H, W13, KP_H, Hdim, KP_H,
            b1, nullptr, 0, nullptr, 0, u3, Hdim, 1, nullptr, nullptr);
        hmma_gemm<<<dim3(Hdim / 128, MY), blk, SMEM_DYN>>>(
            u3, KP_H, W23, KP_H, Hdim, KP_H,
            b2, h, Hdim, h, Hdim, h3, Hdim, 2, nullptr, nullptr);
    }

    // K4: out = h@Wf^T + bf (N=268)
    hmma_gemm<<<dim3((Sdim + 127) / 128, MY), blk, SMEM_DYN>>>(
        h3, KP_H, wf3, KP_H, Sdim, KP_H,
        bf, nullptr, 0, out, Sdim, nullptr, 0, 3, nullptr, nullptr);

    // K5: v2 = state[:, :256]@ta_in[512:768]^T + b -> v23
    hmma_gemm<<<dim3(Adim / 128, MY), blk, SMEM_DYN>>>(
        sp3, KP_S, tain3, KP_A, Adim, KP_A,
        ta_in_b + 2 * Adim, nullptr, 0, nullptr, 0, v23, Adim, 3, nullptr, nullptr);

    // K6: out[:, :256] += 0.1*((v2@ta_out^T + b) - state[:, :256])
    hmma_gemm<<<dim3(Adim / 128, MY), blk, SMEM_DYN>>>(
        v23, KP_A, taout3, KP_A, Adim, KP_A,
        ta_out_b, state, Sdim, out, Sdim, nullptr, 0, 5, nullptr, nullptr);

    // K7: loc path
    loc_kernel<<<Bsz / 256, 256>>>(state, out,
                                   loc_proj_w, loc_proj_b,
                                   lp_in_w, lp_in_b,
                                   lp_out_w, lp_out_b,
                                   loc_back_w, loc_back_b);
}

// round 17
// speedup vs baseline: 2.4184x; 1.1624x over previous
#include <cuda_runtime.h>
#include <cuda_bf16.h>
#include <cstdint>
#include <math.h>

// ---------------- problem constants ----------------
#define Bsz 8192
#define Sdim 268
#define Hdim 1024
#define Rn 8
#define Adim 256
#define SPADK 320           // state/W0 logical K padded to mult of 64

// ---------------- device scratch (allocation-free) ----------------
__device__ __nv_bfloat16 g_sp_hi[(size_t)Bsz * SPADK];
__device__ __nv_bfloat16 g_sp_lo[(size_t)Bsz * SPADK];
__device__ __nv_bfloat16 g_h_hi [(size_t)Bsz * Hdim];
__device__ __nv_bfloat16 g_h_lo [(size_t)Bsz * Hdim];
__device__ __nv_bfloat16 g_u_hi [(size_t)Bsz * Hdim];
__device__ __nv_bfloat16 g_u_lo [(size_t)Bsz * Hdim];
__device__ __nv_bfloat16 g_v2_hi[(size_t)Bsz * Adim];
__device__ __nv_bfloat16 g_v2_lo[(size_t)Bsz * Adim];
__device__ __nv_bfloat16 g_w0_hi[(size_t)Hdim * SPADK];
__device__ __nv_bfloat16 g_w0_lo[(size_t)Hdim * SPADK];
__device__ __nv_bfloat16 g_rw1_hi[(size_t)Rn * Hdim * Hdim];
__device__ __nv_bfloat16 g_rw1_lo[(size_t)Rn * Hdim * Hdim];
__device__ __nv_bfloat16 g_rw2_hi[(size_t)Rn * Hdim * Hdim];
__device__ __nv_bfloat16 g_rw2_lo[(size_t)Rn * Hdim * Hdim];
__device__ __nv_bfloat16 g_wf_hi[(size_t)Sdim * Hdim];
__device__ __nv_bfloat16 g_wf_lo[(size_t)Sdim * Hdim];
__device__ __nv_bfloat16 g_tain_hi[(size_t)Adim * Adim];
__device__ __nv_bfloat16 g_tain_lo[(size_t)Adim * Adim];
__device__ __nv_bfloat16 g_taout_hi[(size_t)Adim * Adim];
__device__ __nv_bfloat16 g_taout_lo[(size_t)Adim * Adim];

// ---------------- helpers ----------------
__device__ __forceinline__ void split_bf16(float x, __nv_bfloat16& hi, __nv_bfloat16& lo) {
    hi = __float2bfloat16(x);
    lo = __float2bfloat16(x - __bfloat162float(hi));
}
__device__ __forceinline__ uint32_t smem_u32(const void* p) {
    uint32_t a;
    asm("{ .reg .u64 t; cvta.to.shared.u64 t, %1; cvt.u32.u64 %0, t; }" : "=r"(a) : "l"(p));
    return a;
}
__device__ __forceinline__ void cp16(uint32_t dst, const void* src, uint32_t sz) {
    asm volatile("cp.async.cg.shared.global [%0], [%1], 16, %2;"
                 :: "r"(dst), "l"(src), "r"(sz) : "memory");
}
__device__ __forceinline__ void ldm4(uint32_t& r0, uint32_t& r1, uint32_t& r2, uint32_t& r3, uint32_t a) {
    asm volatile("ldmatrix.sync.aligned.m8n8.x4.shared.b16 {%0,%1,%2,%3}, [%4];"
                 : "=r"(r0), "=r"(r1), "=r"(r2), "=r"(r3) : "r"(a));
}
__device__ __forceinline__ void mma16816(float* d, const uint32_t* a, const uint32_t* b) {
    asm volatile("mma.sync.aligned.m16n8k16.row.col.f32.bf16.bf16.f32 "
                 "{%0,%1,%2,%3}, {%4,%5,%6,%7}, {%8,%9}, {%0,%1,%2,%3};"
                 : "+f"(d[0]), "+f"(d[1]), "+f"(d[2]), "+f"(d[3])
                 : "r"(a[0]), "r"(a[1]), "r"(a[2]), "r"(a[3]), "r"(b[0]), "r"(b[1]));
}

// ---------------- conversion: 8 logical k per thread -> hi[] and lo[] ----------------
__global__ void conv8(const float* __restrict__ src,
                      __nv_bfloat16* __restrict__ dhi, __nv_bfloat16* __restrict__ dlo,
                      int rows, int src_ld, int src_cols, int Klog)
{
    const int per = Klog >> 3;
    size_t n = (size_t)rows * per;
    size_t stride = (size_t)gridDim.x * blockDim.x;
    for (size_t i = (size_t)blockIdx.x * blockDim.x + threadIdx.x; i < n; i += stride) {
        int r = (int)(i / per);
        int k0 = (int)(i % per) * 8;
        const float* s = src + (size_t)r * src_ld + k0;
        __nv_bfloat16 oh[8], ol[8];
#pragma unroll
        for (int j = 0; j < 8; j++) {
            int k = k0 + j;
            float x = (k < src_cols) ? s[j] : 0.0f;
            split_bf16(x, oh[j], ol[j]);
        }
        *(uint4*)(dhi + (size_t)r * Klog + k0) = *(const uint4*)oh;
        *(uint4*)(dlo + (size_t)r * Klog + k0) = *(const uint4*)ol;
    }
}

// ---------------- HMMA GEMM, block-interleaved 3-pass split-bf16 ----------------
// C(MxN) = A(MxK)*B(NxK)^T via pass0: Ahi.Bhi, pass1: Ahi.Blo, pass2: Alo.Bhi.
// CTA 128x128, KC=64, 2-stage cp.async double buffer, 8 warps of 32x64.
// modes: 0 relu(D+time+bias) -> Ohi/Olo
//        1 tanh(D+bias)      -> Ohi/Olo
//        2 tanh(auxhi+auxlo+D+bias) -> Ohi/Olo (aux pair, may alias O)
//        3 D+bias            -> Cf and/or Ohi/Olo
//        5 Cf += 0.1*(D+bias - auxf)
#define KC 64
#define ROWB 144
#define TILEB (128 * ROWB)
#define STAGEB (2 * TILEB)         // 36864
#define SMEM_DYN (2 * STAGEB)      // 73728

__global__ __launch_bounds__(256)
void hmma_gemm(const __nv_bfloat16* __restrict__ Ahi, const __nv_bfloat16* __restrict__ Alo, int lda,
               const __nv_bfloat16* __restrict__ Bhi, const __nv_bfloat16* __restrict__ Blo, int ldb,
               int N, int Klog,
               const float* __restrict__ bias,
               const float* __restrict__ auxf, int aux_ld,
               const __nv_bfloat16* __restrict__ auxhi, const __nv_bfloat16* __restrict__ auxlo,
               float* __restrict__ Cf, int ldc,
               __nv_bfloat16* __restrict__ Ohi, __nv_bfloat16* __restrict__ Olo, int ldo,
               int mode,
               const float* __restrict__ W0f32, const float* __restrict__ tptr)
{
    extern __shared__ char smem[];
    const uint32_t sbase = smem_u32(smem);
    const int tid = threadIdx.x;
    const int lane = tid & 31, wid = tid >> 5;
    const int bm = blockIdx.y * 128;
    const int bn = blockIdx.x * 128;
    const int warp_m = (wid & 3) * 32;
    const int warp_n = (wid >> 2) * 64;

    uint32_t a_off[2], b_off[4];
#pragma unroll
    for (int t = 0; t < 2; t++)
        a_off[t] = (uint32_t)(warp_m + t * 16 + (lane & 15)) * ROWB + (uint32_t)(lane >> 4) * 16;
#pragma unroll
    for (int p = 0; p < 4; p++)
        b_off[p] = (uint32_t)(warp_n + p * 16 + ((lane >> 4) << 3) + (lane & 7)) * ROWB
                 + (uint32_t)((lane >> 3) & 1) * 16;

    float acc[2][8][4];
#pragma unroll
    for (int t = 0; t < 2; t++)
#pragma unroll
        for (int j = 0; j < 8; j++)
#pragma unroll
            for (int e = 0; e < 4; e++) acc[t][j][e] = 0.0f;

    const int nch3 = Klog / KC;      // chunks per pass
    const int nch = 3 * nch3;        // total chunks
    const int lrow = tid >> 3;
    const int lkv = tid & 7;

#define ISSUE_LOADS(cc) do {                                                        \
        const int _c = (cc);                                                        \
        const int _r = (_c >= 2 * nch3) ? 2 : ((_c >= nch3) ? 1 : 0);               \
        const int _k0 = (_c - _r * nch3) * KC;                                      \
        const __nv_bfloat16* _A = (_r == 2) ? Alo : Ahi;                            \
        const __nv_bfloat16* _B = (_r == 1) ? Blo : Bhi;                            \
        const uint32_t stg = sbase + (_c & 1) * STAGEB;                             \
        _Pragma("unroll")                                                           \
        for (int j = 0; j < 4; j++) {                                               \
            int row = lrow + j * 32;                                                \
            uint32_t d = stg + (uint32_t)row * ROWB + (uint32_t)lkv * 16;           \
            cp16(d, _A + (size_t)(bm + row) * lda + _k0 + lkv * 8, 16);             \
        }                                                                           \
        _Pragma("unroll")                                                           \
        for (int j = 0; j < 4; j++) {                                               \
            int row = lrow + j * 32;                                                \
            int n0 = bn + row;                                                      \
            int nc = n0 < N ? n0 : (N - 1);                                         \
            uint32_t d = stg + TILEB + (uint32_t)row * ROWB + (uint32_t)lkv * 16;   \
            cp16(d, _B + (size_t)nc * ldb + _k0 + lkv * 8, n0 < N ? 16u : 0u);      \
        }                                                                           \
        asm volatile("cp.async.commit_group;" ::: "memory");                        \
    } while (0)

    ISSUE_LOADS(0);

    for (int c = 0; c < nch; c++) {
        if (c + 1 < nch) {
            ISSUE_LOADS(c + 1);
            asm volatile("cp.async.wait_group 1;" ::: "memory");
        } else {
            asm volatile("cp.async.wait_group 0;" ::: "memory");
        }
        __syncthreads();

        const uint32_t sA = sbase + (c & 1) * STAGEB;
        const uint32_t sB = sA + TILEB;
#pragma unroll
        for (int ks = 0; ks < 4; ks++) {
            uint32_t a[2][4];
            ldm4(a[0][0], a[0][1], a[0][2], a[0][3], sA + a_off[0] + ks * 32);
            ldm4(a[1][0], a[1][1], a[1][2], a[1][3], sA + a_off[1] + ks * 32);
            uint32_t bb[4][4];
#pragma unroll
            for (int p = 0; p < 4; p++)
                ldm4(bb[p][0], bb[p][1], bb[p][2], bb[p][3], sB + b_off[p] + ks * 32);
#pragma unroll
            for (int t = 0; t < 2; t++)
#pragma unroll
                for (int j = 0; j < 8; j++)
                    mma16816(acc[t][j], a[t], &bb[j >> 1][(j & 1) * 2]);
        }
        __syncthreads();
    }

    // ---------------- epilogue ----------------
    float sv = 0.0f, cv = 0.0f;
    if (mode == 0) {
        float ang = tptr[0] * (2.0f * 3.14159265358979323846f / 24.0f);
        sv = sinf(ang); cv = cosf(ang);
    }
    const int mrow0 = bm + warp_m + (lane >> 2);
    const int ncol0 = bn + warp_n + (lane & 3) * 2;

#pragma unroll
    for (int t = 0; t < 2; t++)
#pragma unroll
        for (int j = 0; j < 8; j++)
#pragma unroll
            for (int half = 0; half < 2; half++) {
                int m = mrow0 + t * 16 + half * 8;
#pragma unroll
                for (int e = 0; e < 2; e++) {
                    int n = ncol0 + j * 8 + e;
                    if (n >= N) continue;
                    float v = acc[t][j][half * 2 + e] + bias[n];
                    if (mode == 0) {
                        v += sv * W0f32[(size_t)n * (Sdim + 2) + Sdim]
                           + cv * W0f32[(size_t)n * (Sdim + 2) + Sdim + 1];
                        v = fmaxf(v, 0.0f);
                    } else if (mode == 1) {
                        v = tanhf(v);
                    } else if (mode == 2) {
                        size_t ai = (size_t)m * aux_ld + n;
                        v = tanhf(__bfloat162float(auxhi[ai]) + __bfloat162float(auxlo[ai]) + v);
                    } else if (mode == 5) {
                        Cf[(size_t)m * ldc + n] += 0.1f * (v - auxf[(size_t)m * aux_ld + n]);
                        continue;
                    }
                    if (Cf) Cf[(size_t)m * ldc + n] = v;
                    if (Ohi) {
                        __nv_bfloat16 hh, ll; split_bf16(v, hh, ll);
                        size_t oi = (size_t)m * ldo + n;
                        Ohi[oi] = hh; Olo[oi] = ll;
                    }
                }
            }
}

// ---------------- tiny local path (Z=8, E=4) ----------------
__global__ void loc_kernel(
    const float* __restrict__ state, float* __restrict__ out,
    const float* __restrict__ loc_proj_w, const float* __restrict__ loc_proj_b,
    const float* __restrict__ lp_in_w,   const float* __restrict__ lp_in_b,
    const float* __restrict__ lp_out_w,  const float* __restrict__ lp_out_b,
    const float* __restrict__ loc_back_w,const float* __restrict__ loc_back_b)
{
    int m = blockIdx.x * blockDim.x + threadIdx.x;
    if (m >= Bsz) return;
    float loc[8];
#pragma unroll
    for (int j = 0; j < 8; j++) loc[j] = state[(size_t)m * Sdim + Adim + j];
    float lp[4];
#pragma unroll
    for (int i = 0; i < 4; i++) {
        float a = loc_proj_b[i];
#pragma unroll
        for (int j = 0; j < 8; j++) a += loc_proj_w[i * 8 + j] * loc[j];
        lp[i] = a;
    }
    float v[4];
#pragma unroll
    for (int i = 0; i < 4; i++) {
        float a = lp_in_b[8 + i];
#pragma unroll
        for (int j = 0; j < 4; j++) a += lp_in_w[(8 + i) * 4 + j] * lp[j];
        v[i] = a;
    }
    float d[4];
#pragma unroll
    for (int i = 0; i < 4; i++) {
        float a = lp_out_b[i];
#pragma unroll
        for (int j = 0; j < 4; j++) a += lp_out_w[i * 4 + j] * v[j];
        d[i] = a - lp[i];
    }
#pragma unroll
    for (int i = 0; i < 8; i++) {
        float a = loc_back_b[i];
#pragma unroll
        for (int j = 0; j < 4; j++) a += loc_back_w[i * 4 + j] * d[j];
        out[(size_t)m * Sdim + Adim + i] += 0.1f * a;
    }
}

// ---------------- launch ----------------
extern "C" void kernel_launch(void* const* d_in, const int* in_sizes, int n_in,
                              void* d_out, int out_size)
{
    const float* t          = (const float*)d_in[0];
    const float* state      = (const float*)d_in[1];
    const float* W0         = (const float*)d_in[2];
    const float* b0         = (const float*)d_in[3];
    const float* res_W1     = (const float*)d_in[4];
    const float* res_b1     = (const float*)d_in[5];
    const float* res_W2     = (const float*)d_in[6];
    const float* res_b2     = (const float*)d_in[7];
    const float* Wf         = (const float*)d_in[8];
    const float* bf         = (const float*)d_in[9];
    const float* lp_in_w    = (const float*)d_in[10];
    const float* lp_in_b    = (const float*)d_in[11];
    const float* lp_out_w   = (const float*)d_in[12];
    const float* lp_out_b   = (const float*)d_in[13];
    const float* ta_in_w    = (const float*)d_in[14];
    const float* ta_in_b    = (const float*)d_in[15];
    const float* ta_out_w   = (const float*)d_in[16];
    const float* ta_out_b   = (const float*)d_in[17];
    const float* loc_proj_w = (const float*)d_in[18];
    const float* loc_proj_b = (const float*)d_in[19];
    const float* loc_back_w = (const float*)d_in[20];
    const float* loc_back_b = (const float*)d_in[21];
    float* out = (float*)d_out;

    __nv_bfloat16 *sp_hi,*sp_lo,*h_hi,*h_lo,*u_hi,*u_lo,*v2_hi,*v2_lo;
    __nv_bfloat16 *w0_hi,*w0_lo,*rw1_hi,*rw1_lo,*rw2_hi,*rw2_lo,*wf_hi,*wf_lo;
    __nv_bfloat16 *tain_hi,*tain_lo,*taout_hi,*taout_lo;
    cudaGetSymbolAddress((void**)&sp_hi,   g_sp_hi);
    cudaGetSymbolAddress((void**)&sp_lo,   g_sp_lo);
    cudaGetSymbolAddress((void**)&h_hi,    g_h_hi);
    cudaGetSymbolAddress((void**)&h_lo,    g_h_lo);
    cudaGetSymbolAddress((void**)&u_hi,    g_u_hi);
    cudaGetSymbolAddress((void**)&u_lo,    g_u_lo);
    cudaGetSymbolAddress((void**)&v2_hi,   g_v2_hi);
    cudaGetSymbolAddress((void**)&v2_lo,   g_v2_lo);
    cudaGetSymbolAddress((void**)&w0_hi,   g_w0_hi);
    cudaGetSymbolAddress((void**)&w0_lo,   g_w0_lo);
    cudaGetSymbolAddress((void**)&rw1_hi,  g_rw1_hi);
    cudaGetSymbolAddress((void**)&rw1_lo,  g_rw1_lo);
    cudaGetSymbolAddress((void**)&rw2_hi,  g_rw2_hi);
    cudaGetSymbolAddress((void**)&rw2_lo,  g_rw2_lo);
    cudaGetSymbolAddress((void**)&wf_hi,   g_wf_hi);
    cudaGetSymbolAddress((void**)&wf_lo,   g_wf_lo);
    cudaGetSymbolAddress((void**)&tain_hi, g_tain_hi);
    cudaGetSymbolAddress((void**)&tain_lo, g_tain_lo);
    cudaGetSymbolAddress((void**)&taout_hi,g_taout_hi);
    cudaGetSymbolAddress((void**)&taout_lo,g_taout_lo);

    cudaFuncSetAttribute(hmma_gemm, cudaFuncAttributeMaxDynamicSharedMemorySize, SMEM_DYN);

    const int MY = Bsz / 128; // 64
    dim3 blk(256);
    int tb = 256;

    // ---- conversions (all upfront — frozen launch structure) ----
    conv8<<<1280, tb>>>(state, sp_hi, sp_lo, Bsz, Sdim, Sdim, SPADK);
    conv8<<<160,  tb>>>(W0, w0_hi, w0_lo, Hdim, Sdim + 2, Sdim, SPADK);
    conv8<<<2048, tb>>>(res_W1, rw1_hi, rw1_lo, Rn * Hdim, Hdim, Hdim, Hdim);
    conv8<<<2048, tb>>>(res_W2, rw2_hi, rw2_lo, Rn * Hdim, Hdim, Hdim, Hdim);
    conv8<<<136,  tb>>>(Wf, wf_hi, wf_lo, Sdim, Hdim, Hdim, Hdim);
    conv8<<<32,   tb>>>(ta_in_w + (size_t)2 * Adim * Adim, tain_hi, tain_lo, Adim, Adim, Adim, Adim);
    conv8<<<32,   tb>>>(ta_out_w, taout_hi, taout_lo, Adim, Adim, Adim, Adim);

    // K1: h = relu(state@W0^T + time + b0) -> h pair
    hmma_gemm<<<dim3(Hdim / 128, MY), blk, SMEM_DYN>>>(
        sp_hi, sp_lo, SPADK, w0_hi, w0_lo, SPADK, Hdim, SPADK,
        b0, nullptr, 0, nullptr, nullptr, nullptr, 0, h_hi, h_lo, Hdim, 0, W0, t);

    // residual scan
    for (int r = 0; r < Rn; r++) {
        const __nv_bfloat16* W1h = rw1_hi + (size_t)r * Hdim * Hdim;
        const __nv_bfloat16* W1l = rw1_lo + (size_t)r * Hdim * Hdim;
        const __nv_bfloat16* W2h = rw2_hi + (size_t)r * Hdim * Hdim;
        const __nv_bfloat16* W2l = rw2_lo + (size_t)r * Hdim * Hdim;
        const float* b1 = res_b1 + (size_t)r * Hdim;
        const float* b2 = res_b2 + (size_t)r * Hdim;
        // u = tanh(h@W1^T + b1) -> u pair
        hmma_gemm<<<dim3(Hdim / 128, MY), blk, SMEM_DYN>>>(
            h_hi, h_lo, Hdim, W1h, W1l, Hdim, Hdim, Hdim,
            b1, nullptr, 0, nullptr, nullptr, nullptr, 0, u_hi, u_lo, Hdim, 1, nullptr, nullptr);
        // h = tanh(h + u@W2^T + b2) -> h pair (aux = old h pair, same-thread RMW)
        hmma_gemm<<<dim3(Hdim / 128, MY), blk, SMEM_DYN>>>(
            u_hi, u_lo, Hdim, W2h, W2l, Hdim, Hdim, Hdim,
            b2, nullptr, Hdim, h_hi, h_lo, nullptr, 0, h_hi, h_lo, Hdim, 2, nullptr, nullptr);
    }

    // K4: out = h@Wf^T + bf (N=268)
    hmma_gemm<<<dim3((Sdim + 127) / 128, MY), blk, SMEM_DYN>>>(
        h_hi, h_lo, Hdim, wf_hi, wf_lo, Hdim, Sdim, Hdim,
        bf, nullptr, 0, nullptr, nullptr, out, Sdim, nullptr, nullptr, 0, 3, nullptr, nullptr);

    // K5: v2 = state[:, :256]@ta_in[512:768]^T + b -> v2 pair
    hmma_gemm<<<dim3(Adim / 128, MY), blk, SMEM_DYN>>>(
        sp_hi, sp_lo, SPADK, tain_hi, tain_lo, Adim, Adim, Adim,
        ta_in_b + 2 * Adim, nullptr, 0, nullptr, nullptr, nullptr, 0, v2_hi, v2_lo, Adim, 3, nullptr, nullptr);

    // K6: out[:, :256] += 0.1*((v2@ta_out^T + b) - state[:, :256])
    hmma_gemm<<<dim3(Adim / 128, MY), blk, SMEM_DYN>>>(
        v2_hi, v2_lo, Adim, taout_hi, taout_lo, Adim, Adim, Adim,
        ta_out_b, state, Sdim, nullptr, nullptr, out, Sdim, nullptr, nullptr, 0, 5, nullptr, nullptr);

    // K7: loc path
    loc_kernel<<<Bsz / 256, 256>>>(state, out,
                                   loc_proj_w, loc_proj_b,
                                   lp_in_w, lp_in_b,
                                   lp_out_w, lp_out_b,
                                   loc_back_w, loc_back_b);
}